// round 15
// baseline (speedup 1.0000x reference)
#include <cuda_runtime.h>
#include <cuda_fp16.h>
#include <stdint.h>

// ---------------------------------------------------------------------------
// Problem constants
// ---------------------------------------------------------------------------
static constexpr int IN_DIM   = 4096;   // K
static constexpr int OUT_DIM  = 4096;   // N
static constexpr int N_TOKENS = 8192;   // M
static constexpr int RANK     = 16;
static constexpr float LORA_SCALE = 2.0f;   // ALPHA / RANK

// GEMM tiling (round-12 proven, 599.8 us): CTA 128x128, 8 warps (2m x 4n),
// warp tile 64x32, BK=64, 3-stage, 2 CTAs/SM, frag double buffering.
static constexpr int BM = 128;
static constexpr int BN = 128;
static constexpr int BK = 64;                       // halves (128 B rows)
static constexpr int NIT = IN_DIM / BK;             // 64
static constexpr int A_TILE = BM * BK * 2;          // 16 KB
static constexpr int B_TILE = BN * BK * 2;          // 16 KB
static constexpr int STAGE  = A_TILE + B_TILE;      // 32 KB
static constexpr int SMEM_DYN = 3 * STAGE;          // 96 KB

// dequant tiling
static constexpr int OB = 16;     // o-rows per dequant block
static constexpr int IB = 512;    // i-cols per dequant block
static constexpr int DQ_SMEM = RANK * IB * 4;       // 32 KB (A slice)

// NF4 codebook
__constant__ float c_nf4[16] = {
    -1.0f, -0.6961928009986877f, -0.5250730514526367f, -0.39491748809814453f,
    -0.28444138169288635f, -0.18477343022823334f, -0.09105003625154495f, 0.0f,
    0.07958029955625534f, 0.16093020141124725f, 0.24611230194568634f,
    0.33791524171829224f, 0.44070982933044434f, 0.5626170039176941f,
    0.7229568362236023f, 1.0f};

// fp16 scratch: W_eff (32 MB) and x (64 MB)
__device__ __half g_weffh[(size_t)OUT_DIM * IN_DIM];
__device__ __half g_xh[(size_t)N_TOKENS * IN_DIM];

// ---------------------------------------------------------------------------
// Helpers
// ---------------------------------------------------------------------------
__device__ __forceinline__ uint32_t smem_u32(const void* p) {
    uint32_t a;
    asm("{ .reg .u64 t; cvta.to.shared.u64 t, %1; cvt.u32.u64 %0, t; }"
        : "=r"(a) : "l"(p));
    return a;
}
__device__ __forceinline__ void cp_async16(uint32_t dst, const void* src) {
    asm volatile("cp.async.cg.shared.global [%0], [%1], 16;" :: "r"(dst), "l"(src));
}
__device__ __forceinline__ void cp_commit() {
    asm volatile("cp.async.commit_group;" ::: "memory");
}
template <int N>
__device__ __forceinline__ void cp_wait() {
    asm volatile("cp.async.wait_group %0;" :: "n"(N) : "memory");
}
__device__ __forceinline__ void ldmatrix_x4(uint32_t& r0, uint32_t& r1,
                                            uint32_t& r2, uint32_t& r3,
                                            uint32_t addr) {
    asm volatile("ldmatrix.sync.aligned.m8n8.x4.shared.b16 {%0,%1,%2,%3}, [%4];"
                 : "=r"(r0), "=r"(r1), "=r"(r2), "=r"(r3) : "r"(addr));
}
__device__ __forceinline__ void mma_f16(
    float& c0, float& c1, float& c2, float& c3,
    uint32_t a0, uint32_t a1, uint32_t a2, uint32_t a3,
    uint32_t b0, uint32_t b1)
{
    asm volatile(
        "mma.sync.aligned.m16n8k16.row.col.f32.f16.f16.f32 "
        "{%0,%1,%2,%3}, {%4,%5,%6,%7}, {%8,%9}, {%0,%1,%2,%3};"
        : "+f"(c0), "+f"(c1), "+f"(c2), "+f"(c3)
        : "r"(a0), "r"(a1), "r"(a2), "r"(a3), "r"(b0), "r"(b1));
}

// smem tile: row-major, 128 B rows, 8 chunks of 16 B, XOR-swizzled by (row&7).
__device__ __forceinline__ uint32_t swz(int row, int chunk) {
    return (uint32_t)(row * 128 + ((chunk ^ (row & 7)) << 4));
}

// ---------------------------------------------------------------------------
// Kernel 1a: NF4 dequant + LoRA fold -> fp16 W_eff.
// A-slice fill via cp.async (overlaps with codes/scaler/B-row LDGs).
// ---------------------------------------------------------------------------
__global__ __launch_bounds__(256) void dequant_fold_kernel(
    const int4*  __restrict__ codes4,
    const float* __restrict__ scalers,
    const float* __restrict__ Aw,   // [RANK, IN_DIM]
    const float* __restrict__ Bw)   // [OUT_DIM, RANK]
{
    extern __shared__ float As[];             // [RANK][IB]
    float4* As4 = (float4*)As;                // [RANK][IB/4]
    const uint32_t as_base = smem_u32(As);

    const int tid = threadIdx.x;
    const int i0  = (blockIdx.x & (IN_DIM / IB - 1)) * IB;
    const int o0  = (blockIdx.x >> 3) * OB;

    // A-slice fill via cp.async: RANK*IB/4 = 2048 float4, 8 per thread
    const float* Awg = Aw;
#pragma unroll
    for (int j = 0; j < (RANK * IB / 4) / 256; j++) {
        int idx4 = tid + j * 256;
        int r    = idx4 >> 7;                 // /(IB/4)
        int c4   = idx4 & 127;
        cp_async16(as_base + (uint32_t)(r * (IB / 4) + c4) * 16,
                   Awg + (size_t)r * IN_DIM + i0 + c4 * 4);
    }
    cp_commit();

    // overlapping LDGs: codes (both chunks), scaler, B row
    const int o_local = tid & 15;
    const int ig      = tid >> 4;             // 0..15 -> 32 i-elems each
    const int o       = o0 + o_local;
    const size_t base = (size_t)o * IN_DIM + i0 + ig * 32;

    int4 cd[8];
#pragma unroll
    for (int j = 0; j < 8; j++) cd[j] = codes4[(base >> 2) + j];
    const float sc = scalers[base >> 6];

    float breg[RANK];
    {
        const float4* Bw4 = (const float4*)(Bw + (o << 4));
#pragma unroll
        for (int f = 0; f < 4; f++) {
            float4 v = Bw4[f];
            breg[f * 4 + 0] = v.x; breg[f * 4 + 1] = v.y;
            breg[f * 4 + 2] = v.z; breg[f * 4 + 3] = v.w;
        }
    }

    cp_wait<0>();
    __syncthreads();

#pragma unroll
    for (int c = 0; c < 2; c++) {             // 2 chunks x 16 elems
        float4 acc[4];
#pragma unroll
        for (int j = 0; j < 4; j++) acc[j] = make_float4(0.f, 0.f, 0.f, 0.f);
#pragma unroll
        for (int r = 0; r < RANK; r++) {
            float b = breg[r];
            const float4* ar = As4 + r * (IB / 4) + ig * 8 + c * 4;
#pragma unroll
            for (int j = 0; j < 4; j++) {
                float4 a = ar[j];
                acc[j].x = fmaf(b, a.x, acc[j].x);
                acc[j].y = fmaf(b, a.y, acc[j].y);
                acc[j].z = fmaf(b, a.z, acc[j].z);
                acc[j].w = fmaf(b, a.w, acc[j].w);
            }
        }
        uint4 packed[2];
#pragma unroll
        for (int j = 0; j < 4; j++) {
            int4 q = cd[c * 4 + j];
            float w0 = c_nf4[q.x] * sc;
            float w1 = c_nf4[q.y] * sc;
            float w2 = c_nf4[q.z] * sc;
            float w3 = c_nf4[q.w] * sc;
            __half2 h0 = __floats2half2_rn(fmaf(LORA_SCALE, acc[j].x, w0),
                                           fmaf(LORA_SCALE, acc[j].y, w1));
            __half2 h1 = __floats2half2_rn(fmaf(LORA_SCALE, acc[j].z, w2),
                                           fmaf(LORA_SCALE, acc[j].w, w3));
            ((uint32_t*)packed)[j * 2 + 0] = *(uint32_t*)&h0;
            ((uint32_t*)packed)[j * 2 + 1] = *(uint32_t*)&h1;
        }
        *(uint4*)(g_weffh + base + c * 16 + 0) = packed[0];
        *(uint4*)(g_weffh + base + c * 16 + 8) = packed[1];
    }
}

// ---------------------------------------------------------------------------
// Kernel 1b: x -> fp16 (16 elements / thread; lean regs, no smem -> high occ)
// ---------------------------------------------------------------------------
__global__ __launch_bounds__(256) void x_to_half_kernel(const float4* __restrict__ x4)
{
    int idx = blockIdx.x * 256 + threadIdx.x;
    float4 v0 = x4[idx * 4 + 0];
    float4 v1 = x4[idx * 4 + 1];
    float4 v2 = x4[idx * 4 + 2];
    float4 v3 = x4[idx * 4 + 3];
    uint4 p0, p1;
    __half2 h;
    h = __floats2half2_rn(v0.x, v0.y); p0.x = *(uint32_t*)&h;
    h = __floats2half2_rn(v0.z, v0.w); p0.y = *(uint32_t*)&h;
    h = __floats2half2_rn(v1.x, v1.y); p0.z = *(uint32_t*)&h;
    h = __floats2half2_rn(v1.z, v1.w); p0.w = *(uint32_t*)&h;
    h = __floats2half2_rn(v2.x, v2.y); p1.x = *(uint32_t*)&h;
    h = __floats2half2_rn(v2.z, v2.w); p1.y = *(uint32_t*)&h;
    h = __floats2half2_rn(v3.x, v3.y); p1.z = *(uint32_t*)&h;
    h = __floats2half2_rn(v3.z, v3.w); p1.w = *(uint32_t*)&h;
    *(uint4*)(g_xh + (size_t)idx * 16 + 0) = p0;
    *(uint4*)(g_xh + (size_t)idx * 16 + 8) = p1;
}

// ---------------------------------------------------------------------------
// Kernel 2: fp16 mma.sync GEMM (round-12 proven, 599.8 us). UNCHANGED.
// ---------------------------------------------------------------------------
__global__ __launch_bounds__(256, 2)
void gemm_f16_kernel(float* __restrict__ C)
{
    extern __shared__ char dynb[];
    const uint32_t sbase = smem_u32(dynb);

    const int tid   = threadIdx.x;
    const int wid   = tid >> 5;
    const int lane  = tid & 31;
    const int warpm = wid & 1;
    const int warpn = wid >> 1;

    const int brow = blockIdx.y * BM;
    const int bcol = blockIdx.x * BN;

    const __half* Agb = g_xh    + (size_t)brow * IN_DIM;
    const __half* Bgb = g_weffh + (size_t)bcol * IN_DIM;

    auto load_stage = [&](int stage, int kb) {
        const uint32_t sA = sbase + stage * STAGE;
        const uint32_t sB = sA + A_TILE;
#pragma unroll
        for (int i = 0; i < 4; i++) {
            int idx = tid + i * 256;
            int row = idx >> 3;
            int ch  = idx & 7;
            cp_async16(sA + swz(row, ch), Agb + (size_t)row * IN_DIM + kb + ch * 8);
        }
#pragma unroll
        for (int i = 0; i < 4; i++) {
            int idx = tid + i * 256;
            int row = idx >> 3;
            int ch  = idx & 7;
            cp_async16(sB + swz(row, ch), Bgb + (size_t)row * IN_DIM + kb + ch * 8);
        }
        cp_commit();
    };

    const int g   = lane >> 3;
    const int lr8 = lane & 7;
    const int a_row_off = ((g & 1) << 3) + lr8;
    const int a_ch_off  = g >> 1;
    const int b_row_off = ((g >> 1) << 3) + lr8;
    const int b_ch_off  = g & 1;

    auto load_frags = [&](uint32_t (&af)[4][4], uint32_t (&bf)[4][2],
                          uint32_t sA, int ks) {
        const uint32_t sB = sA + A_TILE;
#pragma unroll
        for (int mt = 0; mt < 4; mt++) {
            const int row = warpm * 64 + mt * 16 + a_row_off;
            ldmatrix_x4(af[mt][0], af[mt][1], af[mt][2], af[mt][3],
                        sA + swz(row, 2 * ks + a_ch_off));
        }
#pragma unroll
        for (int bt = 0; bt < 2; bt++) {
            const int row = warpn * 32 + bt * 16 + b_row_off;
            ldmatrix_x4(bf[2 * bt][0], bf[2 * bt][1],
                        bf[2 * bt + 1][0], bf[2 * bt + 1][1],
                        sB + swz(row, 2 * ks + b_ch_off));
        }
    };

    float acc[4][4][4];
#pragma unroll
    for (int mt = 0; mt < 4; mt++)
#pragma unroll
        for (int nt = 0; nt < 4; nt++)
#pragma unroll
            for (int r = 0; r < 4; r++) acc[mt][nt][r] = 0.0f;

    uint32_t af[2][4][4];
    uint32_t bf[2][4][2];

    load_stage(0, 0);
    load_stage(1, BK);
    cp_wait<1>();
    __syncthreads();
    load_frags(af[0], bf[0], sbase, 0);

    int s_cur = 0;
    for (int it = 0; it < NIT; ++it) {
        const uint32_t sA = sbase + s_cur * STAGE;
        const int s_nxt = (s_cur == 2) ? 0 : s_cur + 1;

#pragma unroll
        for (int ks = 0; ks < 4; ks++) {
            const int cur = ks & 1;
            const int nxt = cur ^ 1;

            if (ks < 3) {
                load_frags(af[nxt], bf[nxt], sA, ks + 1);
            } else if (it + 1 < NIT) {
                cp_wait<0>();
                __syncthreads();
                if (it + 2 < NIT) {
                    const int s_pre = (s_nxt == 2) ? 0 : s_nxt + 1;
                    load_stage(s_pre, (it + 2) * BK);
                }
                load_frags(af[nxt], bf[nxt], sbase + s_nxt * STAGE, 0);
            }

#pragma unroll
            for (int mt = 0; mt < 4; mt++)
#pragma unroll
                for (int nt = 0; nt < 4; nt++)
                    mma_f16(acc[mt][nt][0], acc[mt][nt][1],
                            acc[mt][nt][2], acc[mt][nt][3],
                            af[cur][mt][0], af[cur][mt][1],
                            af[cur][mt][2], af[cur][mt][3],
                            bf[cur][nt][0], bf[cur][nt][1]);
        }

        s_cur = s_nxt;
    }

    // epilogue
    const int lr = lane >> 2;
    const int lk = lane & 3;
#pragma unroll
    for (int mt = 0; mt < 4; mt++) {
        const int r0 = brow + warpm * 64 + mt * 16 + lr;
#pragma unroll
        for (int nt = 0; nt < 4; nt++) {
            const int ccol = bcol + warpn * 32 + nt * 8 + 2 * lk;
            *(float2*)(C + (size_t)r0       * OUT_DIM + ccol) =
                make_float2(acc[mt][nt][0], acc[mt][nt][1]);
            *(float2*)(C + (size_t)(r0 + 8) * OUT_DIM + ccol) =
                make_float2(acc[mt][nt][2], acc[mt][nt][3]);
        }
    }
}

// ---------------------------------------------------------------------------
// Launch
// ---------------------------------------------------------------------------
extern "C" void kernel_launch(void* const* d_in, const int* in_sizes, int n_in,
                              void* d_out, int out_size)
{
    const float*  x       = (const float*) d_in[0];
    const int4*   codes   = (const int4*)  d_in[1];
    const float*  scalers = (const float*) d_in[2];
    const float*  Aw      = (const float*) d_in[3];
    const float*  Bw      = (const float*) d_in[4];
    float*        out     = (float*)d_out;

    static bool attr_set = false;
    if (!attr_set) {
        cudaFuncSetAttribute(gemm_f16_kernel,
                             cudaFuncAttributeMaxDynamicSharedMemorySize, SMEM_DYN);
        cudaFuncSetAttribute(dequant_fold_kernel,
                             cudaFuncAttributeMaxDynamicSharedMemorySize, DQ_SMEM);
        attr_set = true;
    }

    // 1a) W_eff fp16 (dequant + LoRA fold), cp.async A-slice fill
    {
        dim3 grid((IN_DIM / IB) * (OUT_DIM / OB));   // 2048
        dequant_fold_kernel<<<grid, 256, DQ_SMEM>>>(codes, scalers, Aw, Bw);
    }

    // 1b) x fp16 (lean kernel, high occupancy)
    x_to_half_kernel<<<((size_t)N_TOKENS * IN_DIM / 16) / 256, 256>>>((const float4*)x);

    // 2) fp16 mma GEMM, 2 CTAs/SM
    {
        dim3 grid(OUT_DIM / BN, N_TOKENS / BM);   // (32, 64)
        gemm_f16_kernel<<<grid, 256, SMEM_DYN>>>(out);
    }
}

// round 16
// speedup vs baseline: 1.0088x; 1.0088x over previous
#include <cuda_runtime.h>
#include <cuda_fp16.h>
#include <stdint.h>

// ---------------------------------------------------------------------------
// Problem constants
// ---------------------------------------------------------------------------
static constexpr int IN_DIM   = 4096;   // K
static constexpr int OUT_DIM  = 4096;   // N
static constexpr int N_TOKENS = 8192;   // M
static constexpr int RANK     = 16;
static constexpr float LORA_SCALE = 2.0f;   // ALPHA / RANK

// GEMM tiling (round-12 proven, 599.8 us): CTA 128x128, 8 warps (2m x 4n),
// warp tile 64x32, BK=64, 3-stage, 2 CTAs/SM, frag double buffering.
static constexpr int BM = 128;
static constexpr int BN = 128;
static constexpr int BK = 64;                       // halves (128 B rows)
static constexpr int NIT = IN_DIM / BK;             // 64
static constexpr int A_TILE = BM * BK * 2;          // 16 KB
static constexpr int B_TILE = BN * BK * 2;          // 16 KB
static constexpr int STAGE  = A_TILE + B_TILE;      // 32 KB
static constexpr int SMEM_DYN = 3 * STAGE;          // 96 KB

// dequant tiling
static constexpr int OB = 16;     // o-rows per dequant block
static constexpr int IB = 512;    // i-cols per dequant block
static constexpr int DQ_SMEM = RANK * IB * 4;       // 32 KB (A slice)
static constexpr int DQ_BLOCKS = (IN_DIM / IB) * (OUT_DIM / OB);   // 2048
static constexpr int XC_BLOCKS = (N_TOKENS * IN_DIM / 16) / 256;   // 8192

// NF4 codebook
__constant__ float c_nf4[16] = {
    -1.0f, -0.6961928009986877f, -0.5250730514526367f, -0.39491748809814453f,
    -0.28444138169288635f, -0.18477343022823334f, -0.09105003625154495f, 0.0f,
    0.07958029955625534f, 0.16093020141124725f, 0.24611230194568634f,
    0.33791524171829224f, 0.44070982933044434f, 0.5626170039176941f,
    0.7229568362236023f, 1.0f};

// fp16 scratch: W_eff (32 MB) and x (64 MB)
__device__ __half g_weffh[(size_t)OUT_DIM * IN_DIM];
__device__ __half g_xh[(size_t)N_TOKENS * IN_DIM];

// ---------------------------------------------------------------------------
// Helpers
// ---------------------------------------------------------------------------
__device__ __forceinline__ uint32_t smem_u32(const void* p) {
    uint32_t a;
    asm("{ .reg .u64 t; cvta.to.shared.u64 t, %1; cvt.u32.u64 %0, t; }"
        : "=r"(a) : "l"(p));
    return a;
}
__device__ __forceinline__ void cp_async16(uint32_t dst, const void* src) {
    asm volatile("cp.async.cg.shared.global [%0], [%1], 16;" :: "r"(dst), "l"(src));
}
__device__ __forceinline__ void cp_commit() {
    asm volatile("cp.async.commit_group;" ::: "memory");
}
template <int N>
__device__ __forceinline__ void cp_wait() {
    asm volatile("cp.async.wait_group %0;" :: "n"(N) : "memory");
}
__device__ __forceinline__ void ldmatrix_x4(uint32_t& r0, uint32_t& r1,
                                            uint32_t& r2, uint32_t& r3,
                                            uint32_t addr) {
    asm volatile("ldmatrix.sync.aligned.m8n8.x4.shared.b16 {%0,%1,%2,%3}, [%4];"
                 : "=r"(r0), "=r"(r1), "=r"(r2), "=r"(r3) : "r"(addr));
}
__device__ __forceinline__ void mma_f16(
    float& c0, float& c1, float& c2, float& c3,
    uint32_t a0, uint32_t a1, uint32_t a2, uint32_t a3,
    uint32_t b0, uint32_t b1)
{
    asm volatile(
        "mma.sync.aligned.m16n8k16.row.col.f32.f16.f16.f32 "
        "{%0,%1,%2,%3}, {%4,%5,%6,%7}, {%8,%9}, {%0,%1,%2,%3};"
        : "+f"(c0), "+f"(c1), "+f"(c2), "+f"(c3)
        : "r"(a0), "r"(a1), "r"(a2), "r"(a3), "r"(b0), "r"(b1));
}

// smem tile: row-major, 128 B rows, 8 chunks of 16 B, XOR-swizzled by (row&7).
__device__ __forceinline__ uint32_t swz(int row, int chunk) {
    return (uint32_t)(row * 128 + ((chunk ^ (row & 7)) << 4));
}

// ---------------------------------------------------------------------------
// Kernel 1 (fused precompute, round-14 structure + round-15 cp.async A-fill):
//   blocks [0, DQ_BLOCKS)          : NF4 dequant + LoRA fold -> g_weffh
//   blocks [DQ_BLOCKS, +XC_BLOCKS) : x fp32 -> fp16 -> g_xh
// ---------------------------------------------------------------------------
__global__ __launch_bounds__(256) void precompute_kernel(
    const int4*   __restrict__ codes4,
    const float*  __restrict__ scalers,
    const float*  __restrict__ Aw,   // [RANK, IN_DIM]
    const float*  __restrict__ Bw,   // [OUT_DIM, RANK]
    const float4* __restrict__ x4)   // [N_TOKENS * IN_DIM / 4]
{
    const int tid = threadIdx.x;

    if (blockIdx.x < DQ_BLOCKS) {
        extern __shared__ float As[];             // [RANK][IB]
        float4* As4 = (float4*)As;                // [RANK][IB/4]
        const uint32_t as_base = smem_u32(As);

        const int bid = blockIdx.x;
        const int i0  = (bid & (IN_DIM / IB - 1)) * IB;
        const int o0  = (bid >> 3) * OB;

        // A-slice fill via cp.async (no register round-trip; overlaps the
        // codes/scaler/B-row LDGs below)
#pragma unroll
        for (int j = 0; j < (RANK * IB / 4) / 256; j++) {
            int idx4 = tid + j * 256;
            int r    = idx4 >> 7;                 // /(IB/4)
            int c4   = idx4 & 127;
            cp_async16(as_base + (uint32_t)(r * (IB / 4) + c4) * 16,
                       Aw + (size_t)r * IN_DIM + i0 + c4 * 4);
        }
        cp_commit();

        const int o_local = tid & 15;
        const int ig      = tid >> 4;             // 0..15 -> 32 i-elems each
        const int o       = o0 + o_local;
        const size_t base = (size_t)o * IN_DIM + i0 + ig * 32;

        // overlapping LDGs while the A-slice streams in
        int4 cd[8];
#pragma unroll
        for (int j = 0; j < 8; j++) cd[j] = codes4[(base >> 2) + j];
        const float sc = scalers[base >> 6];

        float breg[RANK];
        {
            const float4* Bw4 = (const float4*)(Bw + (o << 4));
#pragma unroll
            for (int f = 0; f < 4; f++) {
                float4 v = Bw4[f];
                breg[f * 4 + 0] = v.x; breg[f * 4 + 1] = v.y;
                breg[f * 4 + 2] = v.z; breg[f * 4 + 3] = v.w;
            }
        }

        cp_wait<0>();
        __syncthreads();

#pragma unroll
        for (int c = 0; c < 2; c++) {             // 2 chunks x 16 elems
            float4 acc[4];
#pragma unroll
            for (int j = 0; j < 4; j++) acc[j] = make_float4(0.f, 0.f, 0.f, 0.f);
#pragma unroll
            for (int r = 0; r < RANK; r++) {
                float b = breg[r];
                const float4* ar = As4 + r * (IB / 4) + ig * 8 + c * 4;
#pragma unroll
                for (int j = 0; j < 4; j++) {
                    float4 a = ar[j];
                    acc[j].x = fmaf(b, a.x, acc[j].x);
                    acc[j].y = fmaf(b, a.y, acc[j].y);
                    acc[j].z = fmaf(b, a.z, acc[j].z);
                    acc[j].w = fmaf(b, a.w, acc[j].w);
                }
            }
            uint4 packed[2];
#pragma unroll
            for (int j = 0; j < 4; j++) {
                int4 q = cd[c * 4 + j];
                float w0 = c_nf4[q.x] * sc;
                float w1 = c_nf4[q.y] * sc;
                float w2 = c_nf4[q.z] * sc;
                float w3 = c_nf4[q.w] * sc;
                __half2 h0 = __floats2half2_rn(fmaf(LORA_SCALE, acc[j].x, w0),
                                               fmaf(LORA_SCALE, acc[j].y, w1));
                __half2 h1 = __floats2half2_rn(fmaf(LORA_SCALE, acc[j].z, w2),
                                               fmaf(LORA_SCALE, acc[j].w, w3));
                ((uint32_t*)packed)[j * 2 + 0] = *(uint32_t*)&h0;
                ((uint32_t*)packed)[j * 2 + 1] = *(uint32_t*)&h1;
            }
            *(uint4*)(g_weffh + base + c * 16 + 0) = packed[0];
            *(uint4*)(g_weffh + base + c * 16 + 8) = packed[1];
        }
    } else {
        // ---------------- x -> fp16 (16 elements / thread) -----------------
        int idx = (blockIdx.x - DQ_BLOCKS) * 256 + tid;
        uint4 p[2];
#pragma unroll
        for (int h = 0; h < 2; h++) {
            float4 v0 = x4[idx * 4 + h * 2 + 0];
            float4 v1 = x4[idx * 4 + h * 2 + 1];
            __half2 h0 = __floats2half2_rn(v0.x, v0.y);
            __half2 h1 = __floats2half2_rn(v0.z, v0.w);
            __half2 h2 = __floats2half2_rn(v1.x, v1.y);
            __half2 h3 = __floats2half2_rn(v1.z, v1.w);
            p[h].x = *(uint32_t*)&h0;
            p[h].y = *(uint32_t*)&h1;
            p[h].z = *(uint32_t*)&h2;
            p[h].w = *(uint32_t*)&h3;
        }
        *(uint4*)(g_xh + (size_t)idx * 16 + 0) = p[0];
        *(uint4*)(g_xh + (size_t)idx * 16 + 8) = p[1];
    }
}

// ---------------------------------------------------------------------------
// Kernel 2: fp16 mma.sync GEMM (round-12 proven, 599.8 us). UNCHANGED.
// CTA 128x128, 8 warps (2m x 4n), warp tile 64x32, BK=64, 3-stage, 2 CTAs/SM.
// Double-buffered fragments; barrier + next-stage frag load precede the last
// k-step's MMAs so they are latency-covered.
// ---------------------------------------------------------------------------
__global__ __launch_bounds__(256, 2)
void gemm_f16_kernel(float* __restrict__ C)
{
    extern __shared__ char dynb[];
    const uint32_t sbase = smem_u32(dynb);

    const int tid   = threadIdx.x;
    const int wid   = tid >> 5;
    const int lane  = tid & 31;
    const int warpm = wid & 1;
    const int warpn = wid >> 1;

    const int brow = blockIdx.y * BM;
    const int bcol = blockIdx.x * BN;

    const __half* Agb = g_xh    + (size_t)brow * IN_DIM;
    const __half* Bgb = g_weffh + (size_t)bcol * IN_DIM;

    auto load_stage = [&](int stage, int kb) {
        const uint32_t sA = sbase + stage * STAGE;
        const uint32_t sB = sA + A_TILE;
#pragma unroll
        for (int i = 0; i < 4; i++) {
            int idx = tid + i * 256;
            int row = idx >> 3;
            int ch  = idx & 7;
            cp_async16(sA + swz(row, ch), Agb + (size_t)row * IN_DIM + kb + ch * 8);
        }
#pragma unroll
        for (int i = 0; i < 4; i++) {
            int idx = tid + i * 256;
            int row = idx >> 3;
            int ch  = idx & 7;
            cp_async16(sB + swz(row, ch), Bgb + (size_t)row * IN_DIM + kb + ch * 8);
        }
        cp_commit();
    };

    const int g   = lane >> 3;
    const int lr8 = lane & 7;
    const int a_row_off = ((g & 1) << 3) + lr8;
    const int a_ch_off  = g >> 1;
    const int b_row_off = ((g >> 1) << 3) + lr8;
    const int b_ch_off  = g & 1;

    auto load_frags = [&](uint32_t (&af)[4][4], uint32_t (&bf)[4][2],
                          uint32_t sA, int ks) {
        const uint32_t sB = sA + A_TILE;
#pragma unroll
        for (int mt = 0; mt < 4; mt++) {
            const int row = warpm * 64 + mt * 16 + a_row_off;
            ldmatrix_x4(af[mt][0], af[mt][1], af[mt][2], af[mt][3],
                        sA + swz(row, 2 * ks + a_ch_off));
        }
#pragma unroll
        for (int bt = 0; bt < 2; bt++) {
            const int row = warpn * 32 + bt * 16 + b_row_off;
            ldmatrix_x4(bf[2 * bt][0], bf[2 * bt][1],
                        bf[2 * bt + 1][0], bf[2 * bt + 1][1],
                        sB + swz(row, 2 * ks + b_ch_off));
        }
    };

    float acc[4][4][4];
#pragma unroll
    for (int mt = 0; mt < 4; mt++)
#pragma unroll
        for (int nt = 0; nt < 4; nt++)
#pragma unroll
            for (int r = 0; r < 4; r++) acc[mt][nt][r] = 0.0f;

    uint32_t af[2][4][4];
    uint32_t bf[2][4][2];

    load_stage(0, 0);
    load_stage(1, BK);
    cp_wait<1>();
    __syncthreads();
    load_frags(af[0], bf[0], sbase, 0);

    int s_cur = 0;
    for (int it = 0; it < NIT; ++it) {
        const uint32_t sA = sbase + s_cur * STAGE;
        const int s_nxt = (s_cur == 2) ? 0 : s_cur + 1;

#pragma unroll
        for (int ks = 0; ks < 4; ks++) {
            const int cur = ks & 1;
            const int nxt = cur ^ 1;

            if (ks < 3) {
                load_frags(af[nxt], bf[nxt], sA, ks + 1);
            } else if (it + 1 < NIT) {
                cp_wait<0>();
                __syncthreads();
                if (it + 2 < NIT) {
                    const int s_pre = (s_nxt == 2) ? 0 : s_nxt + 1;
                    load_stage(s_pre, (it + 2) * BK);
                }
                load_frags(af[nxt], bf[nxt], sbase + s_nxt * STAGE, 0);
            }

#pragma unroll
            for (int mt = 0; mt < 4; mt++)
#pragma unroll
                for (int nt = 0; nt < 4; nt++)
                    mma_f16(acc[mt][nt][0], acc[mt][nt][1],
                            acc[mt][nt][2], acc[mt][nt][3],
                            af[cur][mt][0], af[cur][mt][1],
                            af[cur][mt][2], af[cur][mt][3],
                            bf[cur][nt][0], bf[cur][nt][1]);
        }

        s_cur = s_nxt;
    }

    // epilogue
    const int lr = lane >> 2;
    const int lk = lane & 3;
#pragma unroll
    for (int mt = 0; mt < 4; mt++) {
        const int r0 = brow + warpm * 64 + mt * 16 + lr;
#pragma unroll
        for (int nt = 0; nt < 4; nt++) {
            const int ccol = bcol + warpn * 32 + nt * 8 + 2 * lk;
            *(float2*)(C + (size_t)r0       * OUT_DIM + ccol) =
                make_float2(acc[mt][nt][0], acc[mt][nt][1]);
            *(float2*)(C + (size_t)(r0 + 8) * OUT_DIM + ccol) =
                make_float2(acc[mt][nt][2], acc[mt][nt][3]);
        }
    }
}

// ---------------------------------------------------------------------------
// Launch
// ---------------------------------------------------------------------------
extern "C" void kernel_launch(void* const* d_in, const int* in_sizes, int n_in,
                              void* d_out, int out_size)
{
    const float*  x       = (const float*) d_in[0];
    const int4*   codes   = (const int4*)  d_in[1];
    const float*  scalers = (const float*) d_in[2];
    const float*  Aw      = (const float*) d_in[3];
    const float*  Bw      = (const float*) d_in[4];
    float*        out     = (float*)d_out;

    static bool attr_set = false;
    if (!attr_set) {
        cudaFuncSetAttribute(gemm_f16_kernel,
                             cudaFuncAttributeMaxDynamicSharedMemorySize, SMEM_DYN);
        cudaFuncSetAttribute(precompute_kernel,
                             cudaFuncAttributeMaxDynamicSharedMemorySize, DQ_SMEM);
        attr_set = true;
    }

    // 1) fused precompute: W_eff fp16 (dequant + LoRA fold) + x fp16
    precompute_kernel<<<DQ_BLOCKS + XC_BLOCKS, 256, DQ_SMEM>>>(
        codes, scalers, Aw, Bw, (const float4*)x);

    // 2) fp16 mma GEMM, 2 CTAs/SM
    {
        dim3 grid(OUT_DIM / BN, N_TOKENS / BM);   // (32, 64)
        gemm_f16_kernel<<<grid, 256, SMEM_DYN>>>(out);
    }
}